// round 6
// baseline (speedup 1.0000x reference)
#include <cuda_runtime.h>

#define TPB 128
#define PTS_PER_BLK (4 * TPB)

// one packed (c,c) float2 per coupling constant: [0,45) = C2, [45,234) = C3
__constant__ float2 cPack[234];
__device__ float2 gPack[234];

// ---------- packed f32x2 primitives ----------
typedef unsigned long long pf;

__device__ __forceinline__ pf f2fma(pf a, pf b, pf c) {
    pf d; asm("fma.rn.f32x2 %0, %1, %2, %3;" : "=l"(d) : "l"(a), "l"(b), "l"(c)); return d;
}
__device__ __forceinline__ pf f2mul(pf a, pf b) {
    pf d; asm("mul.rn.f32x2 %0, %1, %2;" : "=l"(d) : "l"(a), "l"(b)); return d;
}
__device__ __forceinline__ pf f2add(pf a, pf b) {
    pf d; asm("add.rn.f32x2 %0, %1, %2;" : "=l"(d) : "l"(a), "l"(b)); return d;
}
__device__ __forceinline__ pf f2pack(float lo, float hi) {
    pf d; asm("mov.b64 %0, {%1, %2};" : "=l"(d) : "f"(lo), "f"(hi)); return d;
}
__device__ __forceinline__ void f2unpack(pf p, float& lo, float& hi) {
    asm("mov.b64 {%0, %1}, %2;" : "=f"(lo), "=f"(hi) : "l"(p));
}

// ---------- dual-stream (4 points) wrappers: X and Y share the constant ----------
struct P2 { pf x, y; };

__device__ __forceinline__ P2 p2zero() { P2 r; r.x = 0; r.y = 0; return r; }
// acc += c * a    (c = lane-replicated constant, single LDCU feeding both streams)
__device__ __forceinline__ P2 p2fmac(pf c, P2 a, P2 acc) {
    P2 r; r.x = f2fma(c, a.x, acc.x); r.y = f2fma(c, a.y, acc.y); return r;
}
__device__ __forceinline__ P2 p2mulc(pf c, P2 a) {
    P2 r; r.x = f2mul(c, a.x); r.y = f2mul(c, a.y); return r;
}
__device__ __forceinline__ P2 p2fma(P2 a, P2 b, P2 acc) {
    P2 r; r.x = f2fma(a.x, b.x, acc.x); r.y = f2fma(a.y, b.y, acc.y); return r;
}
__device__ __forceinline__ P2 p2mul(P2 a, P2 b) {
    P2 r; r.x = f2mul(a.x, b.x); r.y = f2mul(a.y, b.y); return r;
}
__device__ __forceinline__ P2 p2add(P2 a, P2 b) {
    P2 r; r.x = f2add(a.x, b.x); r.y = f2add(a.y, b.y); return r;
}

__global__ void prep_kernel(const float* __restrict__ C2, const float* __restrict__ C3) {
    int i = threadIdx.x;
    if (i < 45)       { float c = C2[i];      gPack[i] = make_float2(c, c); }
    else if (i < 234) { float c = C3[i - 45]; gPack[i] = make_float2(c, c); }
}

__global__ __launch_bounds__(TPB, 3)
void hop_invariant_kernel(const float* __restrict__ tf,
                          float* __restrict__ out,
                          int N)
{
    __shared__ __align__(16) float sO[PTS_PER_BLK * 13];

    const unsigned long long* cp = reinterpret_cast<const unsigned long long*>(cPack);
#define C2P(i) cp[i]
#define C3P(i) cp[45 + (i)]

    const int tid = threadIdx.x;
    const int blk_start = blockIdx.x * PTS_PER_BLK;
    const int n0 = blk_start + tid;

    if (n0 < N) {
        // ---- load 16 features for 4 points (up to 16 LDG.128 in flight) ----
        float4 z = make_float4(0.f, 0.f, 0.f, 0.f);
        float4 A[4] = {z, z, z, z}, B[4] = {z, z, z, z},
               C[4] = {z, z, z, z}, D[4] = {z, z, z, z};
        {
            const float4* p = reinterpret_cast<const float4*>(tf + (size_t)n0 * 16);
            A[0] = p[0]; A[1] = p[1]; A[2] = p[2]; A[3] = p[3];
        }
        if (n0 + TPB < N) {
            const float4* p = reinterpret_cast<const float4*>(tf + (size_t)(n0 + TPB) * 16);
            B[0] = p[0]; B[1] = p[1]; B[2] = p[2]; B[3] = p[3];
        }
        if (n0 + 2 * TPB < N) {
            const float4* p = reinterpret_cast<const float4*>(tf + (size_t)(n0 + 2 * TPB) * 16);
            C[0] = p[0]; C[1] = p[1]; C[2] = p[2]; C[3] = p[3];
        }
        if (n0 + 3 * TPB < N) {
            const float4* p = reinterpret_cast<const float4*>(tf + (size_t)(n0 + 3 * TPB) * 16);
            D[0] = p[0]; D[1] = p[1]; D[2] = p[2]; D[3] = p[3];
        }

        // ---- pack: stream X = (A,B), stream Y = (C,D) ----
#define PK(fa, fb, fc, fd) { f2pack(fa, fb), f2pack(fc, fd) }
        const P2 s  = PK(A[0].x, B[0].x, C[0].x, D[0].x);
        P2 v[3] = { PK(A[0].y, B[0].y, C[0].y, D[0].y),
                    PK(A[0].z, B[0].z, C[0].z, D[0].z),
                    PK(A[0].w, B[0].w, C[0].w, D[0].w) };
        const P2 q0 = PK(A[1].x, B[1].x, C[1].x, D[1].x);
        const P2 q1 = PK(A[1].y, B[1].y, C[1].y, D[1].y);
        const P2 q2 = PK(A[1].z, B[1].z, C[1].z, D[1].z);
        const P2 q3 = PK(A[1].w, B[1].w, C[1].w, D[1].w);
        const P2 q4 = PK(A[2].x, B[2].x, C[2].x, D[2].x);
        P2 t[7] = { PK(A[2].y, B[2].y, C[2].y, D[2].y),
                    PK(A[2].z, B[2].z, C[2].z, D[2].z),
                    PK(A[2].w, B[2].w, C[2].w, D[2].w),
                    PK(A[3].x, B[3].x, C[3].x, D[3].x),
                    PK(A[3].y, B[3].y, C[3].y, D[3].y),
                    PK(A[3].z, B[3].z, C[3].z, D[3].z),
                    PK(A[3].w, B[3].w, C[3].w, D[3].w) };
#undef PK

        // ---- ah[r] = sum_m C2[r][m] * q[m]  (one LDCU per constant, 2 FFMA2 consumers) ----
        P2 ah[9];
        #pragma unroll
        for (int r = 0; r < 9; r++) {
            P2 acc = p2mulc(C2P(r * 5 + 0), q0);
            acc = p2fmac(C2P(r * 5 + 1), q1, acc);
            acc = p2fmac(C2P(r * 5 + 2), q2, acc);
            acc = p2fmac(C2P(r * 5 + 3), q3, acc);
            acc = p2fmac(C2P(r * 5 + 4), q4, acc);
            ah[r] = acc;
        }

        // ---- stream bh over i; accumulate b (sym), e, I8 ----
        P2 b00 = p2zero(), b01 = p2zero(), b02 = p2zero(),
           b11 = p2zero(), b12 = p2zero(), b22 = p2zero();
        P2 e0 = p2zero(), e1 = p2zero(), e2 = p2zero();
        P2 I8 = p2zero();

        #pragma unroll
        for (int i = 0; i < 3; i++) {
            P2 bh[9];
            #pragma unroll
            for (int r = 0; r < 9; r++) {
                const int base = (i * 9 + r) * 7;
                P2 acc = p2mulc(C3P(base + 0), t[0]);
                acc = p2fmac(C3P(base + 1), t[1], acc);
                acc = p2fmac(C3P(base + 2), t[2], acc);
                acc = p2fmac(C3P(base + 3), t[3], acc);
                acc = p2fmac(C3P(base + 4), t[4], acc);
                acc = p2fmac(C3P(base + 5), t[5], acc);
                acc = p2fmac(C3P(base + 6), t[6], acc);
                bh[r] = acc;
            }

            P2 i8i = p2zero();
            #pragma unroll
            for (int j = 0; j < 3; j++) {
                const P2 bj0 = bh[j * 3 + 0], bj1 = bh[j * 3 + 1], bj2 = bh[j * 3 + 2];
                b00 = p2fma(bj0, bj0, b00);
                b01 = p2fma(bj0, bj1, b01);
                b02 = p2fma(bj0, bj2, b02);
                b11 = p2fma(bj1, bj1, b11);
                b12 = p2fma(bj1, bj2, b12);
                b22 = p2fma(bj2, bj2, b22);
                const P2 ahij = ah[i * 3 + j];
                e0 = p2fma(bj0, ahij, e0);
                e1 = p2fma(bj1, ahij, e1);
                e2 = p2fma(bj2, ahij, e2);
                P2 dj = p2mul(bj0, v[0]);
                dj = p2fma(bj1, v[1], dj);
                dj = p2fma(bj2, v[2], dj);
                i8i = p2fma(v[j], dj, i8i);
            }
            I8 = p2fma(v[i], i8i, I8);
        }

        // ---- a = ah^T ah (symmetric) ----
        P2 a00 = p2zero(), a01 = p2zero(), a02 = p2zero(),
           a11 = p2zero(), a12 = p2zero(), a22 = p2zero();
        #pragma unroll
        for (int i = 0; i < 3; i++) {
            const P2 x = ah[i * 3 + 0], y = ah[i * 3 + 1], zz = ah[i * 3 + 2];
            a00 = p2fma(x, x, a00); a01 = p2fma(x, y, a01); a02 = p2fma(x, zz, a02);
            a11 = p2fma(y, y, a11); a12 = p2fma(y, zz, a12); a22 = p2fma(zz, zz, a22);
        }

        // ---- invariants ----
        P2 I1 = p2mul(v[0], v[0]);
        I1 = p2fma(v[1], v[1], I1);
        I1 = p2fma(v[2], v[2], I1);
        const P2 I2 = p2add(p2add(a00, a11), a22);
        const P2 I4 = p2add(p2add(b00, b11), b22);

        const P2 sum13 = p2add(ah[1], ah[3]);
        const P2 sum26 = p2add(ah[2], ah[6]);
        const P2 sum57 = p2add(ah[5], ah[7]);

        P2 I3 = p2mul(a00, ah[0]);
        I3 = p2fma(a11, ah[4], I3);
        I3 = p2fma(a22, ah[8], I3);
        I3 = p2fma(a01, sum13, I3);
        I3 = p2fma(a02, sum26, I3);
        I3 = p2fma(a12, sum57, I3);

        P2 I10 = p2mul(b00, ah[0]);
        I10 = p2fma(b11, ah[4], I10);
        I10 = p2fma(b22, ah[8], I10);
        I10 = p2fma(b01, sum13, I10);
        I10 = p2fma(b02, sum26, I10);
        I10 = p2fma(b12, sum57, I10);

        P2 w = p2mul(a01, b01);
        w = p2fma(a02, b02, w);
        w = p2fma(a12, b12, w);
        P2 I11 = p2mul(a00, b00);
        I11 = p2fma(a11, b11, I11);
        I11 = p2fma(a22, b22, I11);
        I11 = p2add(I11, p2add(w, w));

        P2 w5 = p2mul(b01, b01);
        w5 = p2fma(b02, b02, w5);
        w5 = p2fma(b12, b12, w5);
        P2 I5 = p2mul(b00, b00);
        I5 = p2fma(b11, b11, I5);
        I5 = p2fma(b22, b22, I5);
        I5 = p2add(I5, p2add(w5, w5));

        const P2 v01 = p2mul(v[0], v[1]);
        const P2 v02 = p2mul(v[0], v[2]);
        const P2 v12 = p2mul(v[1], v[2]);
        P2 w9 = p2mul(v01, b01);
        w9 = p2fma(v02, b02, w9);
        w9 = p2fma(v12, b12, w9);
        P2 I9 = p2mul(p2mul(v[0], v[0]), b00);
        I9 = p2fma(p2mul(v[1], v[1]), b11, I9);
        I9 = p2fma(p2mul(v[2], v[2]), b22, I9);
        I9 = p2add(I9, p2add(w9, w9));

        P2 cv0 = p2mul(ah[0], v[0]);
        P2 cv1 = p2mul(ah[1], v[0]);
        P2 cv2 = p2mul(ah[2], v[0]);
        cv0 = p2fma(ah[3], v[1], cv0); cv1 = p2fma(ah[4], v[1], cv1); cv2 = p2fma(ah[5], v[1], cv2);
        cv0 = p2fma(ah[6], v[2], cv0); cv1 = p2fma(ah[7], v[2], cv1); cv2 = p2fma(ah[8], v[2], cv2);
        P2 I6 = p2mul(cv0, v[0]);
        I6 = p2fma(cv1, v[1], I6);
        I6 = p2fma(cv2, v[2], I6);
        P2 I7 = p2mul(cv0, cv0);
        I7 = p2fma(cv1, cv1, I7);
        I7 = p2fma(cv2, cv2, I7);

        P2 I12 = p2mul(e0, e0);
        I12 = p2fma(e1, e1, I12);
        I12 = p2fma(e2, e2, I12);

        // ---- unpack and stage 4 points into shared ----
        const P2 invs[13] = { s, I1, I2, I3, I4, I5, I6, I7, I8, I9, I10, I11, I12 };
        float* so0 = &sO[tid * 13];
        float* so1 = &sO[(tid + TPB) * 13];
        float* so2 = &sO[(tid + 2 * TPB) * 13];
        float* so3 = &sO[(tid + 3 * TPB) * 13];
        #pragma unroll
        for (int k = 0; k < 13; k++) {
            float lo, hi;
            f2unpack(invs[k].x, lo, hi);
            so0[k] = lo; so1[k] = hi;
            f2unpack(invs[k].y, lo, hi);
            so2[k] = lo; so3[k] = hi;
        }
    }
    __syncthreads();

    // ---- coalesced writeback ----
    const int valid = min(N - blk_start, PTS_PER_BLK);
    float* obase = out + (size_t)blk_start * 13;

    if (valid == PTS_PER_BLK) {
        const float4* src = reinterpret_cast<const float4*>(sO);
        float4* dst = reinterpret_cast<float4*>(obase);
        #pragma unroll
        for (int i = tid; i < (PTS_PER_BLK * 13) / 4; i += TPB)
            dst[i] = src[i];
    } else {
        const int cnt = valid * 13;
        for (int i = tid; i < cnt; i += TPB)
            obase[i] = sO[i];
    }
#undef C2P
#undef C3P
}

extern "C" void kernel_launch(void* const* d_in, const int* in_sizes, int n_in,
                              void* d_out, int out_size)
{
    const float* tf = (const float*)d_in[0];
    const float* C2 = (const float*)d_in[1];
    const float* C3 = (const float*)d_in[2];
    float* out = (float*)d_out;

    // pack constants (c,c) -> constant bank: kernel node + one D2D memcpy node
    prep_kernel<<<1, 256>>>(C2, C3);
    void* gp = nullptr;
    cudaGetSymbolAddress(&gp, gPack);
    cudaMemcpyToSymbolAsync(cPack, gp, 234 * sizeof(float2), 0, cudaMemcpyDeviceToDevice);

    const int N = in_sizes[0] / 16;
    const int blocks = (N + PTS_PER_BLK - 1) / PTS_PER_BLK;
    hop_invariant_kernel<<<blocks, TPB>>>(tf, out, N);
}

// round 7
// speedup vs baseline: 1.1618x; 1.1618x over previous
#include <cuda_runtime.h>

#define TPB 192
#define PTS_PER_BLK (2 * TPB)

// one packed (c,c) float2 per coupling constant: [0,45) = C2, [45,234) = C3
__constant__ float2 cPack[234];
__device__ float2 gPack[234];

// ---------- packed f32x2 helpers ----------
typedef unsigned long long pf;

__device__ __forceinline__ pf f2fma(pf a, pf b, pf c) {
    pf d; asm("fma.rn.f32x2 %0, %1, %2, %3;" : "=l"(d) : "l"(a), "l"(b), "l"(c)); return d;
}
__device__ __forceinline__ pf f2mul(pf a, pf b) {
    pf d; asm("mul.rn.f32x2 %0, %1, %2;" : "=l"(d) : "l"(a), "l"(b)); return d;
}
__device__ __forceinline__ pf f2add(pf a, pf b) {
    pf d; asm("add.rn.f32x2 %0, %1, %2;" : "=l"(d) : "l"(a), "l"(b)); return d;
}
__device__ __forceinline__ pf f2pack(float lo, float hi) {
    pf d; asm("mov.b64 %0, {%1, %2};" : "=l"(d) : "f"(lo), "f"(hi)); return d;
}
__device__ __forceinline__ void f2unpack(pf p, float& lo, float& hi) {
    asm("mov.b64 {%0, %1}, %2;" : "=f"(lo), "=f"(hi) : "l"(p));
}

__global__ void prep_kernel(const float* __restrict__ C2, const float* __restrict__ C3) {
    int i = threadIdx.x;
    if (i < 45)       { float c = C2[i];      gPack[i] = make_float2(c, c); }
    else if (i < 234) { float c = C3[i - 45]; gPack[i] = make_float2(c, c); }
}

__global__ __launch_bounds__(TPB, 4)
void hop_invariant_kernel(const float* __restrict__ tf,
                          float* __restrict__ out,
                          int N)
{
    __shared__ __align__(16) float sO[PTS_PER_BLK * 13];

    const unsigned long long* cp = reinterpret_cast<const unsigned long long*>(cPack);
#define C2P(i) cp[i]
#define C3P(i) cp[45 + (i)]

    const int tid = threadIdx.x;
    const int blk_start = blockIdx.x * PTS_PER_BLK;
    const int nA = blk_start + tid;
    const int nB = nA + TPB;

    if (nA < N) {
        // ---- load 16 features for both points ----
        float4 a0 = make_float4(0,0,0,0), a1 = a0, a2 = a0, a3 = a0;
        float4 b0 = a0, b1 = a0, b2 = a0, b3 = a0;
        {
            const float4* pA = reinterpret_cast<const float4*>(tf + (size_t)nA * 16);
            a0 = pA[0]; a1 = pA[1]; a2 = pA[2]; a3 = pA[3];
        }
        if (nB < N) {
            const float4* pB = reinterpret_cast<const float4*>(tf + (size_t)nB * 16);
            b0 = pB[0]; b1 = pB[1]; b2 = pB[2]; b3 = pB[3];
        }

        // ---- pack lanes: lo = point A, hi = point B ----
        const pf s  = f2pack(a0.x, b0.x);
        pf v[3] = { f2pack(a0.y, b0.y), f2pack(a0.z, b0.z), f2pack(a0.w, b0.w) };
        pf q[5] = { f2pack(a1.x, b1.x), f2pack(a1.y, b1.y),
                    f2pack(a1.z, b1.z), f2pack(a1.w, b1.w), f2pack(a2.x, b2.x) };
        pf t[7] = { f2pack(a2.y, b2.y), f2pack(a2.z, b2.z), f2pack(a2.w, b2.w),
                    f2pack(a3.x, b3.x), f2pack(a3.y, b3.y), f2pack(a3.z, b3.z),
                    f2pack(a3.w, b3.w) };

        // ---- ah[r] = sum_m C2[r][m] * q[m]  (q dies here) ----
        pf ah[9];
        #pragma unroll
        for (int r = 0; r < 9; r++) {
            pf acc = f2mul(C2P(r * 5 + 0), q[0]);
            acc = f2fma(C2P(r * 5 + 1), q[1], acc);
            acc = f2fma(C2P(r * 5 + 2), q[2], acc);
            acc = f2fma(C2P(r * 5 + 3), q[3], acc);
            acc = f2fma(C2P(r * 5 + 4), q[4], acc);
            ah[r] = acc;
        }

        // ---- stream bh 3-at-a-time over (i,j); accumulate b (sym), e, I8 ----
        pf b00 = 0, b01 = 0, b02 = 0, b11 = 0, b12 = 0, b22 = 0;
        pf e0 = 0, e1 = 0, e2 = 0;
        pf I8 = 0;

        #pragma unroll
        for (int i = 0; i < 3; i++) {
            pf i8i = 0;
            #pragma unroll
            for (int j = 0; j < 3; j++) {
                pf bj0, bj1, bj2;
                {
                    const int base = (i * 9 + j * 3) * 7;
                    pf x0 = f2mul(C3P(base + 0), t[0]);
                    pf x1 = f2mul(C3P(base + 7), t[0]);
                    pf x2 = f2mul(C3P(base + 14), t[0]);
                    #pragma unroll
                    for (int m = 1; m < 7; m++) {
                        x0 = f2fma(C3P(base + m),      t[m], x0);
                        x1 = f2fma(C3P(base + 7 + m),  t[m], x1);
                        x2 = f2fma(C3P(base + 14 + m), t[m], x2);
                    }
                    bj0 = x0; bj1 = x1; bj2 = x2;
                }
                // symmetric Gram accumulation
                b00 = f2fma(bj0, bj0, b00);
                b01 = f2fma(bj0, bj1, b01);
                b02 = f2fma(bj0, bj2, b02);
                b11 = f2fma(bj1, bj1, b11);
                b12 = f2fma(bj1, bj2, b12);
                b22 = f2fma(bj2, bj2, b22);
                // e[k] += bh[i][j][k] * ah[i][j]
                const pf ahij = ah[i * 3 + j];
                e0 = f2fma(bj0, ahij, e0);
                e1 = f2fma(bj1, ahij, e1);
                e2 = f2fma(bj2, ahij, e2);
                // I8 partial
                pf dj = f2mul(bj0, v[0]);
                dj = f2fma(bj1, v[1], dj);
                dj = f2fma(bj2, v[2], dj);
                i8i = f2fma(v[j], dj, i8i);
            }
            I8 = f2fma(v[i], i8i, I8);
        }
        // t dead now.

        // ---- a = ah^T ah (symmetric) ----
        pf a00 = 0, a01 = 0, a02 = 0, a11 = 0, a12 = 0, a22 = 0;
        #pragma unroll
        for (int i = 0; i < 3; i++) {
            const pf x = ah[i * 3 + 0], y = ah[i * 3 + 1], z = ah[i * 3 + 2];
            a00 = f2fma(x, x, a00); a01 = f2fma(x, y, a01); a02 = f2fma(x, z, a02);
            a11 = f2fma(y, y, a11); a12 = f2fma(y, z, a12); a22 = f2fma(z, z, a22);
        }

        // ---- invariants (packed) ----
        pf I1 = f2mul(v[0], v[0]);
        I1 = f2fma(v[1], v[1], I1);
        I1 = f2fma(v[2], v[2], I1);
        const pf I2 = f2add(f2add(a00, a11), a22);
        const pf I4 = f2add(f2add(b00, b11), b22);

        const pf sum13 = f2add(ah[1], ah[3]);
        const pf sum26 = f2add(ah[2], ah[6]);
        const pf sum57 = f2add(ah[5], ah[7]);

        pf I3 = f2mul(a00, ah[0]);
        I3 = f2fma(a11, ah[4], I3);
        I3 = f2fma(a22, ah[8], I3);
        I3 = f2fma(a01, sum13, I3);
        I3 = f2fma(a02, sum26, I3);
        I3 = f2fma(a12, sum57, I3);

        pf I10 = f2mul(b00, ah[0]);
        I10 = f2fma(b11, ah[4], I10);
        I10 = f2fma(b22, ah[8], I10);
        I10 = f2fma(b01, sum13, I10);
        I10 = f2fma(b02, sum26, I10);
        I10 = f2fma(b12, sum57, I10);

        pf w = f2mul(a01, b01);
        w = f2fma(a02, b02, w);
        w = f2fma(a12, b12, w);
        pf I11 = f2mul(a00, b00);
        I11 = f2fma(a11, b11, I11);
        I11 = f2fma(a22, b22, I11);
        I11 = f2add(I11, f2add(w, w));

        pf w5 = f2mul(b01, b01);
        w5 = f2fma(b02, b02, w5);
        w5 = f2fma(b12, b12, w5);
        pf I5 = f2mul(b00, b00);
        I5 = f2fma(b11, b11, I5);
        I5 = f2fma(b22, b22, I5);
        I5 = f2add(I5, f2add(w5, w5));

        const pf v01 = f2mul(v[0], v[1]);
        const pf v02 = f2mul(v[0], v[2]);
        const pf v12 = f2mul(v[1], v[2]);
        pf w9 = f2mul(v01, b01);
        w9 = f2fma(v02, b02, w9);
        w9 = f2fma(v12, b12, w9);
        pf I9 = f2mul(f2mul(v[0], v[0]), b00);
        I9 = f2fma(f2mul(v[1], v[1]), b11, I9);
        I9 = f2fma(f2mul(v[2], v[2]), b22, I9);
        I9 = f2add(I9, f2add(w9, w9));

        pf cv0 = f2mul(ah[0], v[0]);
        pf cv1 = f2mul(ah[1], v[0]);
        pf cv2 = f2mul(ah[2], v[0]);
        cv0 = f2fma(ah[3], v[1], cv0); cv1 = f2fma(ah[4], v[1], cv1); cv2 = f2fma(ah[5], v[1], cv2);
        cv0 = f2fma(ah[6], v[2], cv0); cv1 = f2fma(ah[7], v[2], cv1); cv2 = f2fma(ah[8], v[2], cv2);
        pf I6 = f2mul(cv0, v[0]);
        I6 = f2fma(cv1, v[1], I6);
        I6 = f2fma(cv2, v[2], I6);
        pf I7 = f2mul(cv0, cv0);
        I7 = f2fma(cv1, cv1, I7);
        I7 = f2fma(cv2, cv2, I7);

        pf I12 = f2mul(e0, e0);
        I12 = f2fma(e1, e1, I12);
        I12 = f2fma(e2, e2, I12);

        // ---- unpack and stage both points into shared ----
        const pf invs[13] = { s, I1, I2, I3, I4, I5, I6, I7, I8, I9, I10, I11, I12 };
        float* soA = &sO[tid * 13];
        float* soB = &sO[(tid + TPB) * 13];
        #pragma unroll
        for (int k = 0; k < 13; k++) {
            float lo, hi;
            f2unpack(invs[k], lo, hi);
            soA[k] = lo;
            soB[k] = hi;
        }
    }
    __syncthreads();

    // ---- coalesced writeback ----
    const int valid = min(N - blk_start, PTS_PER_BLK);
    float* obase = out + (size_t)blk_start * 13;

    if (valid == PTS_PER_BLK) {
        const float4* src = reinterpret_cast<const float4*>(sO);
        float4* dst = reinterpret_cast<float4*>(obase);
        #pragma unroll
        for (int i = tid; i < (PTS_PER_BLK * 13) / 4; i += TPB)
            dst[i] = src[i];
    } else {
        const int cnt = valid * 13;
        for (int i = tid; i < cnt; i += TPB)
            obase[i] = sO[i];
    }
#undef C2P
#undef C3P
}

extern "C" void kernel_launch(void* const* d_in, const int* in_sizes, int n_in,
                              void* d_out, int out_size)
{
    const float* tf = (const float*)d_in[0];
    const float* C2 = (const float*)d_in[1];
    const float* C3 = (const float*)d_in[2];
    float* out = (float*)d_out;

    // pack constants (c,c) -> constant bank: kernel node + one D2D memcpy node
    prep_kernel<<<1, 256>>>(C2, C3);
    void* gp = nullptr;
    cudaGetSymbolAddress(&gp, gPack);
    cudaMemcpyToSymbolAsync(cPack, gp, 234 * sizeof(float2), 0, cudaMemcpyDeviceToDevice);

    const int N = in_sizes[0] / 16;
    const int blocks = (N + PTS_PER_BLK - 1) / PTS_PER_BLK;
    hop_invariant_kernel<<<blocks, TPB>>>(tf, out, N);
}